// round 7
// baseline (speedup 1.0000x reference)
#include <cuda_runtime.h>
#include <math_constants.h>

#define NCLS    1000
#define NPAD    1024
#define KTOP    5
#define BMAX    64
#define THREADS 512
#define NWARP   16

__device__ float        g_row_loss[BMAX];
__device__ unsigned int g_done_cnt = 0;

// order-preserving float->uint key (monotone), 0 is below any finite key
__device__ __forceinline__ unsigned fkey(float f) {
    unsigned b = __float_as_uint(f);
    return (b & 0x80000000u) ? ~b : (b | 0x80000000u);
}
__device__ __forceinline__ float fdec(unsigned k) {
    unsigned b = (k & 0x80000000u) ? (k & 0x7FFFFFFFu) : ~k;
    return __uint_as_float(b);
}

// bitonic compare-exchange via shuffle; i = global index of this lane's element
__device__ __forceinline__ float shfl_stage(float v, int i, int j, int k) {
    float other = __shfl_xor_sync(0xFFFFFFFFu, v, j);
    bool lower = (i & j) == 0;       // this lane holds the lower global index
    bool desc  = (i & k) == 0;       // run direction (descending final sort)
    float mn = fminf(v, other), mx = fmaxf(v, other);
    return (lower == desc) ? mx : mn;
}

__device__ __forceinline__ void cmpswap(float& a, float& b, bool desc) {
    float mn = fminf(a, b), mx = fmaxf(a, b);
    a = desc ? mx : mn;
    b = desc ? mn : mx;
}

__global__ __launch_bounds__(THREADS)
void topk_fused_kernel(const float* __restrict__ outp,
                       const int*   __restrict__ target,
                       float*       __restrict__ out,
                       int B)
{
    __shared__ float    sval[NPAD];      // sort scratch, later cs1
    __shared__ unsigned sol[NPAD];       // per-j max keys
    __shared__ float    rcp[NPAD + 2];   // 1/len, idx 1..1000
    __shared__ float    wsum[NWARP];
    __shared__ float    red[NWARP];
    __shared__ int      s_p;
    __shared__ float    s_sp;
    __shared__ int      s_last;

    const int tid = threadIdx.x;
    const int w   = tid >> 5;
    const int l   = tid & 31;
    const int i0  = (w << 6) | l;     // this thread's two element positions
    const int i1  = i0 + 32;
    const int b   = blockIdx.x;
    const float* row = outp + (size_t)b * NCLS;
    const int   tgt = target[b];
    const float vt  = __ldg(row + tgt);

    // ---- setup: init shared, load, count p ----
    if (tid == 0) s_p = 0;
    sol[tid]       = 0u;
    sol[tid + 512] = 0u;
    rcp[tid + 1]   = 1.0f / (float)(tid + 1);
    rcp[tid + 513] = 1.0f / (float)(tid + 513);

    float r0 = (i0 < NCLS) ? row[i0] : -CUDART_INF_F;
    float r1 = (i1 < NCLS) ? row[i1] : -CUDART_INF_F;

    int cnt = 0;
    if (i0 < NCLS) cnt += (r0 > vt) || (r0 == vt && i0 < tgt);
    if (i1 < NCLS) cnt += (r1 > vt) || (r1 == vt && i1 < tgt);
    #pragma unroll
    for (int o = 16; o; o >>= 1)
        cnt += __shfl_xor_sync(0xFFFFFFFFu, cnt, o);
    __syncthreads();                  // s_p=0 + sol/rcp init visible
    if (l == 0) atomicAdd(&s_p, cnt);

    // ---- phase A: in-register bitonic, stages k=2..64 (no barriers) ----
    #pragma unroll
    for (int k = 2; k <= 32; k <<= 1) {
        #pragma unroll
        for (int j = k >> 1; j > 0; j >>= 1) {
            r0 = shfl_stage(r0, i0, j, k);
            r1 = shfl_stage(r1, i1, j, k);
        }
    }
    cmpswap(r0, r1, (i0 & 64) == 0);  // k=64, j=32 (intra-thread)
    #pragma unroll
    for (int j = 16; j > 0; j >>= 1) {
        r0 = shfl_stage(r0, i0, j, 64);
        r1 = shfl_stage(r1, i1, j, 64);
    }

    // ---- phase B: k=128..1024; j>=64 in shared, j<=32 in registers ----
    #pragma unroll
    for (int k = 128; k <= NPAD; k <<= 1) {
        sval[i0] = r0;
        sval[i1] = r1;
        __syncthreads();
        for (int j = k >> 1; j >= 64; j >>= 1) {
            #pragma unroll
            for (int t = 0; t < 2; t++) {
                int i = tid + t * THREADS;
                int ixj = i ^ j;
                if (ixj > i) {
                    float v1 = sval[i], v2 = sval[ixj];
                    bool after = v1 < v2;
                    bool sw = ((i & k) == 0) ? after : !after;
                    if (sw) { sval[i] = v2; sval[ixj] = v1; }
                }
            }
            __syncthreads();
        }
        r0 = sval[i0];
        r1 = sval[i1];
        cmpswap(r0, r1, (i0 & k) == 0);
        #pragma unroll
        for (int j = 16; j > 0; j >>= 1) {
            r0 = shfl_stage(r0, i0, j, k);
            r1 = shfl_stage(r1, i1, j, k);
        }
    }
    // r0/r1 now hold globally descending-sorted values at positions i0/i1

    const int p = s_p;                // all atomicAdds drained by phase-B barriers
    if (i0 == p) s_sp = r0;
    if (i1 == p) s_sp = r1;

    // ---- y = s - w, shuffle-based inclusive scan ----
    float y0 = (i0 < NCLS) ? r0 - (float)(NCLS - i0) : 0.0f;
    float y1 = (i1 < NCLS) ? r1 - (float)(NCLS - i1) : 0.0f;

    float s0 = y0;
    #pragma unroll
    for (int o = 1; o < 32; o <<= 1) {
        float t = __shfl_up_sync(0xFFFFFFFFu, s0, o);
        if (l >= o) s0 += t;
    }
    float s1 = y1;
    #pragma unroll
    for (int o = 1; o < 32; o <<= 1) {
        float t = __shfl_up_sync(0xFFFFFFFFu, s1, o);
        if (l >= o) s1 += t;
    }
    s1 += __shfl_sync(0xFFFFFFFFu, s0, 31);
    if (l == 31) wsum[w] = s1;
    __syncthreads();
    if (w == 0) {
        float v = (l < NWARP) ? wsum[l] : 0.0f;
        #pragma unroll
        for (int o = 1; o < 16; o <<= 1) {
            float t = __shfl_up_sync(0xFFFFFFFFu, v, o);
            if (l >= o) v += t;
        }
        if (l < NWARP) wsum[l] = v;
    }
    __syncthreads();
    {
        float off = (w == 0) ? 0.0f : wsum[w - 1];
        sval[i0] = s0 + off;          // sval reused as cs1: cs1[i] = cs[i+1]
        sval[i1] = s1 + off;
    }
    __syncthreads();

    // ---- balanced min-max: warps split k-range, lanes stride j ----
    const float sp  = s_sp;
    const float* cs1 = sval;
    const int nk = NCLS - p;
    const int kb = p + (nk * w) / NWARP;
    const int ke = p + (nk * (w + 1)) / NWARP;

    for (int j = l; j <= p; j += 32) {
        float csj = (j == 0) ? 0.0f : cs1[j - 1];
        float m0 = -CUDART_INF_F, m1 = -CUDART_INF_F;
        int k = kb;
        for (; k + 1 < ke; k += 2) {
            m0 = fmaxf(m0, (cs1[k]     - csj) * rcp[k - j + 1]);
            m1 = fmaxf(m1, (cs1[k + 1] - csj) * rcp[k - j + 2]);
        }
        if (k < ke)
            m0 = fmaxf(m0, (cs1[k] - csj) * rcp[k - j + 1]);
        if (kb < ke)
            atomicMax(&sol[j], fkey(fmaxf(m0, m1)));
    }
    __syncthreads();

    // ---- min over j, block reduce ----
    float gmin = CUDART_INF_F;
    for (int j = tid; j <= p; j += THREADS)
        gmin = fminf(gmin, fdec(sol[j]));
    #pragma unroll
    for (int o = 16; o; o >>= 1)
        gmin = fminf(gmin, __shfl_xor_sync(0xFFFFFFFFu, gmin, o));
    if (l == 0) red[w] = gmin;
    __syncthreads();
    if (tid == 0) {
        float v = CUDART_INF_F;
        #pragma unroll
        for (int i = 0; i < NWARP; i++) v = fminf(v, red[i]);
        float rank = sp - v;
        g_row_loss[b] = fmaxf(0.0f, (float)(NCLS - KTOP + 1) - rank);
        __threadfence();
        unsigned t = atomicAdd(&g_done_cnt, 1u);
        s_last = (t == (unsigned)(B - 1));
    }
    __syncthreads();

    // ---- last CTA reduces row losses and writes the mean ----
    if (s_last && tid < 32) {
        __threadfence();
        float v = 0.0f;
        for (int i = tid; i < B; i += 32)
            v += g_row_loss[i];
        #pragma unroll
        for (int o = 16; o; o >>= 1)
            v += __shfl_xor_sync(0xFFFFFFFFu, v, o);
        if (tid == 0) {
            out[0] = v / (float)B;
            g_done_cnt = 0;           // reset for next graph replay
            __threadfence();
        }
    }
}

extern "C" void kernel_launch(void* const* d_in, const int* in_sizes, int n_in,
                              void* d_out, int out_size)
{
    const float* outp   = (const float*)d_in[0];
    const int*   target = (const int*)d_in[1];
    float*       out    = (float*)d_out;

    int B = in_sizes[1];
    if (B > BMAX) B = BMAX;

    topk_fused_kernel<<<B, THREADS>>>(outp, target, out, B);
}

// round 8
// speedup vs baseline: 1.3449x; 1.3449x over previous
#include <cuda_runtime.h>
#include <math_constants.h>
#include <cub/block/block_radix_sort.cuh>

#define NCLS    1000
#define NPAD    1024
#define KTOP    5
#define BMAX    64
#define THREADS 512
#define NWARP   16

__device__ float        g_row_loss[BMAX];
__device__ unsigned int g_done_cnt = 0;

typedef cub::BlockRadixSort<float, THREADS, 2> BlockSort;

// order-preserving float->uint key (monotone); 0 is below any valid key
__device__ __forceinline__ unsigned fkey(float f) {
    unsigned b = __float_as_uint(f);
    return (b & 0x80000000u) ? ~b : (b | 0x80000000u);
}
__device__ __forceinline__ float fdec(unsigned k) {
    unsigned b = (k & 0x80000000u) ? (k & 0x7FFFFFFFu) : ~k;
    return __uint_as_float(b);
}

__global__ __launch_bounds__(THREADS)
void topk_fused_kernel(const float* __restrict__ outp,
                       const int*   __restrict__ target,
                       float*       __restrict__ out,
                       int B)
{
    __shared__ typename BlockSort::TempStorage sort_tmp;
    __shared__ float    cs1s[NPAD];      // inclusive prefix sums: cs1s[i] = cs[i+1]
    __shared__ unsigned sol[NPAD];       // per-j max keys
    __shared__ float    rcp[NPAD + 2];   // 1/len table, idx 1..1024
    __shared__ float    wsum[NWARP];
    __shared__ float    red[NWARP];
    __shared__ int      s_p;
    __shared__ int      s_last;

    const int tid = threadIdx.x;
    const int w   = tid >> 5;
    const int l   = tid & 31;
    const int b   = blockIdx.x;
    const int i0  = 2 * tid;             // blocked arrangement positions
    const int i1  = 2 * tid + 1;
    const float* row = outp + (size_t)b * NCLS;
    const int   tgt = target[b];
    const float vt  = __ldg(row + tgt);  // == s[p] after stable descending sort

    // ---- init + load (NCLS even -> pair loads never straddle the boundary) ----
    if (tid == 0) s_p = 0;
    sol[tid]            = 0u;
    sol[tid + THREADS]  = 0u;
    rcp[tid + 1]        = 1.0f / (float)(tid + 1);
    rcp[tid + 513]      = 1.0f / (float)(tid + 513);

    float keys[2];
    if (i0 < NCLS) {
        float2 v = *reinterpret_cast<const float2*>(row + i0);
        keys[0] = v.x;
        keys[1] = v.y;
    } else {
        keys[0] = -CUDART_INF_F;
        keys[1] = -CUDART_INF_F;
    }

    // p = #(v > vt) + #(v == vt && i < tgt)  (stable argsort of -theta)
    int cnt = 0;
    if (i0 < NCLS) {
        cnt += (keys[0] > vt) || (keys[0] == vt && i0 < tgt);
        cnt += (keys[1] > vt) || (keys[1] == vt && i1 < tgt);
    }
    #pragma unroll
    for (int o = 16; o; o >>= 1)
        cnt += __shfl_xor_sync(0xFFFFFFFFu, cnt, o);
    __syncthreads();                     // s_p=0 / sol / rcp visible
    if (l == 0) atomicAdd(&s_p, cnt);

    // ---- sort values descending (blocked: thread t holds positions 2t, 2t+1) ----
    BlockSort(sort_tmp).SortDescending(keys);
    // CUB's internal barriers also drain the s_p atomics.

    // ---- y = s - w ; inclusive scan via pair-sum shuffle scan ----
    float y0 = (i0 < NCLS) ? keys[0] - (float)(NCLS - i0) : 0.0f;
    float y1 = (i1 < NCLS) ? keys[1] - (float)(NCLS - i1) : 0.0f;

    float pair = y0 + y1;
    float s = pair;
    #pragma unroll
    for (int o = 1; o < 32; o <<= 1) {
        float t = __shfl_up_sync(0xFFFFFFFFu, s, o);
        if (l >= o) s += t;
    }
    if (l == 31) wsum[w] = s;            // warp total
    __syncthreads();
    if (w == 0) {
        float v = (l < NWARP) ? wsum[l] : 0.0f;
        #pragma unroll
        for (int o = 1; o < 16; o <<= 1) {
            float t = __shfl_up_sync(0xFFFFFFFFu, v, o);
            if (l >= o) v += t;
        }
        if (l < NWARP) wsum[l] = v;
    }
    __syncthreads();
    {
        float off = (w == 0) ? 0.0f : wsum[w - 1];
        float incl = s + off;            // sum through i1
        cs1s[i1] = incl;
        cs1s[i0] = incl - y1;
    }
    __syncthreads();

    // ---- balanced min-max: sol_p = min_{j<=p} max_{k>=p} (cs[k+1]-cs[j])*rcp[k-j+1]
    //      warps partition the k-range, lanes stride j, merge via atomicMax ----
    const int p  = s_p;
    const int nk = NCLS - p;
    const int kb = p + (nk * w) / NWARP;
    const int ke = p + (nk * (w + 1)) / NWARP;

    if (kb < ke) {
        for (int j = l; j <= p; j += 32) {
            float csj = (j == 0) ? 0.0f : cs1s[j - 1];
            const float* rj = rcp + (1 - j);
            float m0 = -CUDART_INF_F, m1 = -CUDART_INF_F;
            int k = kb;
            for (; k + 1 < ke; k += 2) {
                m0 = fmaxf(m0, (cs1s[k]     - csj) * rj[k]);
                m1 = fmaxf(m1, (cs1s[k + 1] - csj) * rj[k + 1]);
            }
            if (k < ke)
                m0 = fmaxf(m0, (cs1s[k] - csj) * rj[k]);
            atomicMax(&sol[j], fkey(fmaxf(m0, m1)));
        }
    }
    __syncthreads();

    // ---- min over j, block reduce ----
    float gmin = CUDART_INF_F;
    for (int j = tid; j <= p; j += THREADS)
        gmin = fminf(gmin, fdec(sol[j]));
    #pragma unroll
    for (int o = 16; o; o >>= 1)
        gmin = fminf(gmin, __shfl_xor_sync(0xFFFFFFFFu, gmin, o));
    if (l == 0) red[w] = gmin;
    __syncthreads();
    if (tid == 0) {
        float v = CUDART_INF_F;
        #pragma unroll
        for (int i = 0; i < NWARP; i++) v = fminf(v, red[i]);
        float rank = vt - v;             // s[p] - sol_p
        g_row_loss[b] = fmaxf(0.0f, (float)(NCLS - KTOP + 1) - rank);
        __threadfence();
        unsigned t = atomicAdd(&g_done_cnt, 1u);
        s_last = (t == (unsigned)(B - 1));
    }
    __syncthreads();

    // ---- last CTA to finish reduces row losses and writes the mean ----
    if (s_last && tid < 32) {
        __threadfence();
        float v = 0.0f;
        for (int i = tid; i < B; i += 32)
            v += g_row_loss[i];
        #pragma unroll
        for (int o = 16; o; o >>= 1)
            v += __shfl_xor_sync(0xFFFFFFFFu, v, o);
        if (tid == 0) {
            out[0] = v / (float)B;
            g_done_cnt = 0;              // reset for next graph replay
            __threadfence();
        }
    }
}

extern "C" void kernel_launch(void* const* d_in, const int* in_sizes, int n_in,
                              void* d_out, int out_size)
{
    const float* outp   = (const float*)d_in[0];
    const int*   target = (const int*)d_in[1];
    float*       out    = (float*)d_out;

    int B = in_sizes[1];
    if (B > BMAX) B = BMAX;

    topk_fused_kernel<<<B, THREADS>>>(outp, target, out, B);
}